// round 2
// baseline (speedup 1.0000x reference)
#include <cuda_runtime.h>
#include <cuda_bf16.h>
#include <cstdint>

// ---------------- shapes (fixed by the problem) ----------------
#define B_   2048
#define F_   32
#define P_   64
#define E_   64
#define H_   128
#define M_   512      // K of GEMM2
#define D_   1024
#define EPSV 1e-5f

// ---------------- device scratch (no allocs allowed) ----------------
__device__ float g_C0[M_];
__device__ float g_C1[M_];
__device__ float g_v[M_];
__device__ float g_s1[M_], g_c1[M_];
__device__ float g_s2[D_], g_c2[D_];
__device__ float g_p[B_ * M_];
__device__ float g_q[B_ * M_];

// ---------------- f32x2 packed helpers (Blackwell) ----------------
__device__ __forceinline__ unsigned long long pk2(float x, float y) {
    unsigned long long r;
    asm("mov.b64 %0, {%1, %2};" : "=l"(r) : "f"(x), "f"(y));
    return r;
}
__device__ __forceinline__ void unpk2(unsigned long long v, float& x, float& y) {
    asm("mov.b64 {%0, %1}, %2;" : "=f"(x), "=f"(y) : "l"(v));
}
__device__ __forceinline__ unsigned long long ffma2(unsigned long long a,
                                                    unsigned long long b,
                                                    unsigned long long c) {
    unsigned long long d;
    asm("fma.rn.f32x2 %0, %1, %2, %3;" : "=l"(d) : "l"(a), "l"(b), "l"(c));
    return d;
}

// ---------------- prep0: fold constants ----------------
// C = We @ W1_top  (2 x 512), v = be @ W1_top, BN1/BN2 affine folds.
__global__ void prep0(const float* __restrict__ We, const float* __restrict__ be,
                      const float* __restrict__ W1,
                      const float* __restrict__ g1, const float* __restrict__ beta1,
                      const float* __restrict__ rm1, const float* __restrict__ rv1,
                      const float* __restrict__ b2, const float* __restrict__ g2,
                      const float* __restrict__ beta2,
                      const float* __restrict__ rm2, const float* __restrict__ rv2) {
    int m = threadIdx.x;  // 512 threads
    float c0 = 0.f, c1 = 0.f, vv = 0.f;
#pragma unroll 8
    for (int e = 0; e < E_; e++) {
        float w = W1[e * M_ + m];
        c0 += We[e] * w;          // We[0][e]
        c1 += We[E_ + e] * w;     // We[1][e]
        vv += be[e] * w;
    }
    g_C0[m] = c0;
    g_C1[m] = c1;
    g_v[m]  = vv;
    float s = g1[m] * rsqrtf(rv1[m] + EPSV);
    g_s1[m] = s;
    g_c1[m] = beta1[m] - s * rm1[m];
    for (int d = m; d < D_; d += M_) {
        float s2 = g2[d] * rsqrtf(rv2[d] + EPSV);
        g_s2[d] = s2;
        g_c2[d] = beta2[d] + s2 * (b2[d] - rm2[d]);
    }
}

// ---------------- prep1: build p,q (B x 512) ----------------
// t[b] = h[b] @ W1_bot; u[b] = pos[b] @ C; p = s1*(u+t+v+b1)+c1; q = s1*u
__global__ void prep1(const float* __restrict__ h, const float* __restrict__ pos,
                      const float* __restrict__ W1, const float* __restrict__ b1) {
    __shared__ float hs[8][H_];
    __shared__ float ps[8][2];
    int tid = threadIdx.x;       // 256
    int b0 = blockIdx.x * 8;     // grid 256
    for (int idx = tid; idx < 8 * H_; idx += 256) {
        int bb = idx >> 7, k = idx & 127;
        hs[bb][k] = h[(b0 + bb) * H_ + k];
    }
    if (tid < 16) ps[tid >> 1][tid & 1] = pos[b0 * 2 + tid];
    __syncthreads();

    int m0 = tid * 2;
    float acc[8][2];
#pragma unroll
    for (int bb = 0; bb < 8; bb++) { acc[bb][0] = 0.f; acc[bb][1] = 0.f; }
#pragma unroll 4
    for (int k = 0; k < H_; k++) {
        float2 w = *(const float2*)&W1[(E_ + k) * M_ + m0];
#pragma unroll
        for (int bb = 0; bb < 8; bb++) {
            float hv = hs[bb][k];
            acc[bb][0] += hv * w.x;
            acc[bb][1] += hv * w.y;
        }
    }
#pragma unroll
    for (int mm = 0; mm < 2; mm++) {
        int m = m0 + mm;
        float C0 = g_C0[m], C1 = g_C1[m], vv = g_v[m];
        float s = g_s1[m], cc = g_c1[m], bb1 = b1[m];
#pragma unroll
        for (int bb = 0; bb < 8; bb++) {
            float u = ps[bb][0] * C0 + ps[bb][1] * C1;
            float a = u + acc[bb][mm] + vv + bb1;
            g_p[(b0 + bb) * M_ + m] = s * a + cc;
            g_q[(b0 + bb) * M_ + m] = s * u;
        }
    }
}

// ---------------- main GEMM2 + max-pool ----------------
// per CTA: (f, i, d-tile of 256). A[j,k] = relu(p[f*64+j,k] - q[f*64+i,k]),
// C = A @ W2_tile (64 x 256), out[i,d] = relu(max_j (s2*C + c2)).
#define KC  16
#define DT  256
#define NCH (M_ / KC)   // 32 K-chunks

__global__ __launch_bounds__(256, 2) void mainK(const float* __restrict__ W2,
                                                float* __restrict__ out) {
    const int dt  = blockIdx.x;   // 0..3
    const int i   = blockIdx.y;   // 0..63
    const int f   = blockIdx.z;   // 0..31
    const int tid = threadIdx.x;
    const int tj  = tid >> 5;     // warp id 0..7 -> j-group of 8
    const int td  = tid & 31;     // lane -> d-group of 8
    const int dbase = dt * DT;

    __shared__ float qs[M_];
    __shared__ float zs[KC][P_];
    __shared__ float ws[KC][DT];
    __shared__ float red[8][DT];

    const float* qrow = g_q + (f * P_ + i) * M_;
    for (int m = tid; m < M_; m += 256) qs[m] = qrow[m];

    const float* prow = g_p + (size_t)(f * P_) * M_;

    // gmem staging thread maps
    const int pj  = tid >> 2;          // 0..63 (j row)
    const int pk4 = (tid & 3) * 4;     // 0,4,8,12 within K-chunk
    const int wk  = tid >> 6;          // 0..3
    const int wd  = (tid & 63) * 4;    // 0..252

    float4 pv;
    float4 wv[4];
    {
        pv = *(const float4*)&prow[pj * M_ + pk4];
#pragma unroll
        for (int r = 0; r < 4; r++)
            wv[r] = *(const float4*)&W2[(size_t)(wk + r * 4) * D_ + dbase + wd];
    }

    unsigned long long acc[8][4];
#pragma unroll
    for (int jj = 0; jj < 8; jj++)
#pragma unroll
        for (int pp = 0; pp < 4; pp++) acc[jj][pp] = 0ull;

    const int j0 = tj * 8;
    const int d0 = td * 8;

    __syncthreads();  // qs ready

    for (int c = 0; c < NCH; c++) {
        // stage current chunk into smem (z = relu(p - q))
        float4 q4 = *(const float4*)&qs[c * KC + pk4];
        zs[pk4 + 0][pj] = fmaxf(pv.x - q4.x, 0.f);
        zs[pk4 + 1][pj] = fmaxf(pv.y - q4.y, 0.f);
        zs[pk4 + 2][pj] = fmaxf(pv.z - q4.z, 0.f);
        zs[pk4 + 3][pj] = fmaxf(pv.w - q4.w, 0.f);
#pragma unroll
        for (int r = 0; r < 4; r++) *(float4*)&ws[wk + r * 4][wd] = wv[r];
        __syncthreads();

        // prefetch next chunk
        if (c + 1 < NCH) {
            int k0 = (c + 1) * KC;
            pv = *(const float4*)&prow[pj * M_ + k0 + pk4];
#pragma unroll
            for (int r = 0; r < 4; r++)
                wv[r] = *(const float4*)&W2[(size_t)(k0 + wk + r * 4) * D_ + dbase + wd];
        }

        // compute
#pragma unroll
        for (int k = 0; k < KC; k++) {
            float4 za = *(const float4*)&zs[k][j0];
            float4 zb = *(const float4*)&zs[k][j0 + 4];
            float4 wa = *(const float4*)&ws[k][d0];
            float4 wb = *(const float4*)&ws[k][d0 + 4];
            unsigned long long w01 = pk2(wa.x, wa.y);
            unsigned long long w23 = pk2(wa.z, wa.w);
            unsigned long long w45 = pk2(wb.x, wb.y);
            unsigned long long w67 = pk2(wb.z, wb.w);
            float zv[8] = {za.x, za.y, za.z, za.w, zb.x, zb.y, zb.z, zb.w};
#pragma unroll
            for (int jj = 0; jj < 8; jj++) {
                unsigned long long zz = pk2(zv[jj], zv[jj]);
                acc[jj][0] = ffma2(zz, w01, acc[jj][0]);
                acc[jj][1] = ffma2(zz, w23, acc[jj][1]);
                acc[jj][2] = ffma2(zz, w45, acc[jj][2]);
                acc[jj][3] = ffma2(zz, w67, acc[jj][3]);
            }
        }
        __syncthreads();
    }

    // epilogue: affine (folded BN2) then max over local 8 j's
    const int d0g = dbase + d0;
    float s2r[8], c2r[8], mx[8];
#pragma unroll
    for (int e = 0; e < 8; e++) {
        s2r[e] = g_s2[d0g + e];
        c2r[e] = g_c2[d0g + e];
        mx[e]  = -3.402823466e38f;
    }
#pragma unroll
    for (int jj = 0; jj < 8; jj++) {
#pragma unroll
        for (int pp = 0; pp < 4; pp++) {
            float x, y;
            unpk2(acc[jj][pp], x, y);
            int e0 = pp * 2;
            mx[e0]     = fmaxf(mx[e0],     s2r[e0]     * x + c2r[e0]);
            mx[e0 + 1] = fmaxf(mx[e0 + 1], s2r[e0 + 1] * y + c2r[e0 + 1]);
        }
    }
#pragma unroll
    for (int e = 0; e < 8; e++) red[tj][d0 + e] = mx[e];
    __syncthreads();
    if (tj == 0) {
#pragma unroll
        for (int e = 0; e < 8; e++) {
            float v = red[0][d0 + e];
#pragma unroll
            for (int w = 1; w < 8; w++) v = fmaxf(v, red[w][d0 + e]);
            out[(size_t)(f * P_ + i) * D_ + d0g + e] = fmaxf(v, 0.f);
        }
    }
}

// ---------------- launch ----------------
extern "C" void kernel_launch(void* const* d_in, const int* in_sizes, int n_in,
                              void* d_out, int out_size) {
    const float* h     = (const float*)d_in[0];   // (1,2048,128)
    const float* pos   = (const float*)d_in[1];   // (2048,2)
    // d_in[2] = seq_start_end (int64) — frames are equal-size, unused
    const float* We    = (const float*)d_in[3];   // (2,64)
    const float* be    = (const float*)d_in[4];   // (64)
    const float* W1    = (const float*)d_in[5];   // (192,512)
    const float* b1    = (const float*)d_in[6];   // (512)
    const float* g1    = (const float*)d_in[7];
    const float* beta1 = (const float*)d_in[8];
    const float* W2    = (const float*)d_in[9];   // (512,1024)
    const float* b2    = (const float*)d_in[10];
    const float* g2    = (const float*)d_in[11];
    const float* beta2 = (const float*)d_in[12];
    const float* rm1   = (const float*)d_in[13];
    const float* rv1   = (const float*)d_in[14];
    const float* rm2   = (const float*)d_in[15];
    const float* rv2   = (const float*)d_in[16];
    float* out = (float*)d_out;                   // (2048,1024)

    prep0<<<1, 512>>>(We, be, W1, g1, beta1, rm1, rv1, b2, g2, beta2, rm2, rv2);
    prep1<<<B_ / 8, 256>>>(h, pos, W1, b1);
    dim3 grid(D_ / DT, P_, F_);
    mainK<<<grid, 256>>>(W2, out);
}

// round 3
// speedup vs baseline: 1.0012x; 1.0012x over previous
#include <cuda_runtime.h>
#include <cuda_bf16.h>
#include <cstdint>

// ---------------- shapes (fixed by the problem) ----------------
#define B_   2048
#define F_   32
#define P_   64
#define E_   64
#define H_   128
#define M_   512      // K of GEMM2
#define D_   1024
#define EPSV 1e-5f

// ---------------- device scratch (no allocs allowed) ----------------
__device__ float g_C0[M_];
__device__ float g_C1[M_];
__device__ float g_v[M_];
__device__ float g_s1[M_], g_c1[M_];
__device__ float g_s2[D_], g_c2[D_];
__device__ float g_p[B_ * M_];
__device__ float g_q[B_ * M_];

// ---------------- f32x2 packed helpers (Blackwell) ----------------
__device__ __forceinline__ unsigned long long pk2(float x, float y) {
    unsigned long long r;
    asm("mov.b64 %0, {%1, %2};" : "=l"(r) : "f"(x), "f"(y));
    return r;
}
__device__ __forceinline__ void unpk2(unsigned long long v, float& x, float& y) {
    asm("mov.b64 {%0, %1}, %2;" : "=f"(x), "=f"(y) : "l"(v));
}
__device__ __forceinline__ unsigned long long ffma2(unsigned long long a,
                                                    unsigned long long b,
                                                    unsigned long long c) {
    unsigned long long d;
    asm("fma.rn.f32x2 %0, %1, %2, %3;" : "=l"(d) : "l"(a), "l"(b), "l"(c));
    return d;
}

// ---------------- prep0: fold constants ----------------
// C = We @ W1_top  (2 x 512), v = be @ W1_top, BN1/BN2 affine folds.
__global__ void prep0(const float* __restrict__ We, const float* __restrict__ be,
                      const float* __restrict__ W1,
                      const float* __restrict__ g1, const float* __restrict__ beta1,
                      const float* __restrict__ rm1, const float* __restrict__ rv1,
                      const float* __restrict__ b2, const float* __restrict__ g2,
                      const float* __restrict__ beta2,
                      const float* __restrict__ rm2, const float* __restrict__ rv2) {
    int m = threadIdx.x;  // 512 threads
    float c0 = 0.f, c1 = 0.f, vv = 0.f;
#pragma unroll 8
    for (int e = 0; e < E_; e++) {
        float w = W1[e * M_ + m];
        c0 += We[e] * w;          // We[0][e]
        c1 += We[E_ + e] * w;     // We[1][e]
        vv += be[e] * w;
    }
    g_C0[m] = c0;
    g_C1[m] = c1;
    g_v[m]  = vv;
    float s = g1[m] * rsqrtf(rv1[m] + EPSV);
    g_s1[m] = s;
    g_c1[m] = beta1[m] - s * rm1[m];
    for (int d = m; d < D_; d += M_) {
        float s2 = g2[d] * rsqrtf(rv2[d] + EPSV);
        g_s2[d] = s2;
        g_c2[d] = beta2[d] + s2 * (b2[d] - rm2[d]);
    }
}

// ---------------- prep1: build p,q (B x 512) ----------------
// t[b] = h[b] @ W1_bot; u[b] = pos[b] @ C; p = s1*(u+t+v+b1)+c1; q = s1*u
__global__ void prep1(const float* __restrict__ h, const float* __restrict__ pos,
                      const float* __restrict__ W1, const float* __restrict__ b1) {
    __shared__ float hs[8][H_];
    __shared__ float ps[8][2];
    int tid = threadIdx.x;       // 256
    int b0 = blockIdx.x * 8;     // grid 256
    for (int idx = tid; idx < 8 * H_; idx += 256) {
        int bb = idx >> 7, k = idx & 127;
        hs[bb][k] = h[(b0 + bb) * H_ + k];
    }
    if (tid < 16) ps[tid >> 1][tid & 1] = pos[b0 * 2 + tid];
    __syncthreads();

    int m0 = tid * 2;
    float acc[8][2];
#pragma unroll
    for (int bb = 0; bb < 8; bb++) { acc[bb][0] = 0.f; acc[bb][1] = 0.f; }
#pragma unroll 4
    for (int k = 0; k < H_; k++) {
        float2 w = *(const float2*)&W1[(E_ + k) * M_ + m0];
#pragma unroll
        for (int bb = 0; bb < 8; bb++) {
            float hv = hs[bb][k];
            acc[bb][0] += hv * w.x;
            acc[bb][1] += hv * w.y;
        }
    }
#pragma unroll
    for (int mm = 0; mm < 2; mm++) {
        int m = m0 + mm;
        float C0 = g_C0[m], C1 = g_C1[m], vv = g_v[m];
        float s = g_s1[m], cc = g_c1[m], bb1 = b1[m];
#pragma unroll
        for (int bb = 0; bb < 8; bb++) {
            float u = ps[bb][0] * C0 + ps[bb][1] * C1;
            float a = u + acc[bb][mm] + vv + bb1;
            g_p[(b0 + bb) * M_ + m] = s * a + cc;
            g_q[(b0 + bb) * M_ + m] = s * u;
        }
    }
}

// ---------------- main GEMM2 + max-pool ----------------
// per CTA: (f, i, d-tile of 256). A[j,k] = relu(p[f*64+j,k] - q[f*64+i,k]),
// C = A @ W2_tile (64 x 256), out[i,d] = relu(max_j (s2*C + c2)).
#define KC  16
#define DT  256
#define NCH (M_ / KC)   // 32 K-chunks

__global__ __launch_bounds__(256, 2) void mainK(const float* __restrict__ W2,
                                                float* __restrict__ out) {
    const int dt  = blockIdx.x;   // 0..3
    const int i   = blockIdx.y;   // 0..63
    const int f   = blockIdx.z;   // 0..31
    const int tid = threadIdx.x;
    const int tj  = tid >> 5;     // warp id 0..7 -> j-group of 8
    const int td  = tid & 31;     // lane -> d-group of 8
    const int dbase = dt * DT;

    __shared__ float qs[M_];
    __shared__ float zs[KC][P_];
    __shared__ float ws[KC][DT];
    __shared__ float red[8][DT];

    const float* qrow = g_q + (f * P_ + i) * M_;
    for (int m = tid; m < M_; m += 256) qs[m] = qrow[m];

    const float* prow = g_p + (size_t)(f * P_) * M_;

    // gmem staging thread maps
    const int pj  = tid >> 2;          // 0..63 (j row)
    const int pk4 = (tid & 3) * 4;     // 0,4,8,12 within K-chunk
    const int wk  = tid >> 6;          // 0..3
    const int wd  = (tid & 63) * 4;    // 0..252

    float4 pv;
    float4 wv[4];
    {
        pv = *(const float4*)&prow[pj * M_ + pk4];
#pragma unroll
        for (int r = 0; r < 4; r++)
            wv[r] = *(const float4*)&W2[(size_t)(wk + r * 4) * D_ + dbase + wd];
    }

    unsigned long long acc[8][4];
#pragma unroll
    for (int jj = 0; jj < 8; jj++)
#pragma unroll
        for (int pp = 0; pp < 4; pp++) acc[jj][pp] = 0ull;

    const int j0 = tj * 8;
    const int d0 = td * 8;

    __syncthreads();  // qs ready

    for (int c = 0; c < NCH; c++) {
        // stage current chunk into smem (z = relu(p - q))
        float4 q4 = *(const float4*)&qs[c * KC + pk4];
        zs[pk4 + 0][pj] = fmaxf(pv.x - q4.x, 0.f);
        zs[pk4 + 1][pj] = fmaxf(pv.y - q4.y, 0.f);
        zs[pk4 + 2][pj] = fmaxf(pv.z - q4.z, 0.f);
        zs[pk4 + 3][pj] = fmaxf(pv.w - q4.w, 0.f);
#pragma unroll
        for (int r = 0; r < 4; r++) *(float4*)&ws[wk + r * 4][wd] = wv[r];
        __syncthreads();

        // prefetch next chunk
        if (c + 1 < NCH) {
            int k0 = (c + 1) * KC;
            pv = *(const float4*)&prow[pj * M_ + k0 + pk4];
#pragma unroll
            for (int r = 0; r < 4; r++)
                wv[r] = *(const float4*)&W2[(size_t)(k0 + wk + r * 4) * D_ + dbase + wd];
        }

        // compute
#pragma unroll
        for (int k = 0; k < KC; k++) {
            float4 za = *(const float4*)&zs[k][j0];
            float4 zb = *(const float4*)&zs[k][j0 + 4];
            float4 wa = *(const float4*)&ws[k][d0];
            float4 wb = *(const float4*)&ws[k][d0 + 4];
            unsigned long long w01 = pk2(wa.x, wa.y);
            unsigned long long w23 = pk2(wa.z, wa.w);
            unsigned long long w45 = pk2(wb.x, wb.y);
            unsigned long long w67 = pk2(wb.z, wb.w);
            float zv[8] = {za.x, za.y, za.z, za.w, zb.x, zb.y, zb.z, zb.w};
#pragma unroll
            for (int jj = 0; jj < 8; jj++) {
                unsigned long long zz = pk2(zv[jj], zv[jj]);
                acc[jj][0] = ffma2(zz, w01, acc[jj][0]);
                acc[jj][1] = ffma2(zz, w23, acc[jj][1]);
                acc[jj][2] = ffma2(zz, w45, acc[jj][2]);
                acc[jj][3] = ffma2(zz, w67, acc[jj][3]);
            }
        }
        __syncthreads();
    }

    // epilogue: affine (folded BN2) then max over local 8 j's
    const int d0g = dbase + d0;
    float s2r[8], c2r[8], mx[8];
#pragma unroll
    for (int e = 0; e < 8; e++) {
        s2r[e] = g_s2[d0g + e];
        c2r[e] = g_c2[d0g + e];
        mx[e]  = -3.402823466e38f;
    }
#pragma unroll
    for (int jj = 0; jj < 8; jj++) {
#pragma unroll
        for (int pp = 0; pp < 4; pp++) {
            float x, y;
            unpk2(acc[jj][pp], x, y);
            int e0 = pp * 2;
            mx[e0]     = fmaxf(mx[e0],     s2r[e0]     * x + c2r[e0]);
            mx[e0 + 1] = fmaxf(mx[e0 + 1], s2r[e0 + 1] * y + c2r[e0 + 1]);
        }
    }
#pragma unroll
    for (int e = 0; e < 8; e++) red[tj][d0 + e] = mx[e];
    __syncthreads();
    if (tj == 0) {
#pragma unroll
        for (int e = 0; e < 8; e++) {
            float v = red[0][d0 + e];
#pragma unroll
            for (int w = 1; w < 8; w++) v = fmaxf(v, red[w][d0 + e]);
            out[(size_t)(f * P_ + i) * D_ + d0g + e] = fmaxf(v, 0.f);
        }
    }
}

// ---------------- launch ----------------
extern "C" void kernel_launch(void* const* d_in, const int* in_sizes, int n_in,
                              void* d_out, int out_size) {
    const float* h     = (const float*)d_in[0];   // (1,2048,128)
    const float* pos   = (const float*)d_in[1];   // (2048,2)
    // d_in[2] = seq_start_end (int64) — frames are equal-size, unused
    const float* We    = (const float*)d_in[3];   // (2,64)
    const float* be    = (const float*)d_in[4];   // (64)
    const float* W1    = (const float*)d_in[5];   // (192,512)
    const float* b1    = (const float*)d_in[6];   // (512)
    const float* g1    = (const float*)d_in[7];
    const float* beta1 = (const float*)d_in[8];
    const float* W2    = (const float*)d_in[9];   // (512,1024)
    const float* b2    = (const float*)d_in[10];
    const float* g2    = (const float*)d_in[11];
    const float* beta2 = (const float*)d_in[12];
    const float* rm1   = (const float*)d_in[13];
    const float* rv1   = (const float*)d_in[14];
    const float* rm2   = (const float*)d_in[15];
    const float* rv2   = (const float*)d_in[16];
    float* out = (float*)d_out;                   // (2048,1024)

    prep0<<<1, 512>>>(We, be, W1, g1, beta1, rm1, rv1, b2, g2, beta2, rm2, rv2);
    prep1<<<B_ / 8, 256>>>(h, pos, W1, b1);
    dim3 grid(D_ / DT, P_, F_);
    mainK<<<grid, 256>>>(W2, out);
}